// round 16
// baseline (speedup 1.0000x reference)
#include <cuda_runtime.h>
#include <cuda_fp16.h>
#include <cstdint>

#define N_NODES  20000
#define N_EDGES  40000
#define N_GRAPHS 500
#define D_IN     32
#define D_E      16
#define H1       100
#define H2       20
#define F1       50
#define H1P      112

// ---------------- scratch (zero-initialized at module load) --------------------
__device__ __align__(128) __half d_xh [(size_t)N_NODES * D_IN];
__device__ __align__(128) __half d_h1h[(size_t)N_NODES * H1P];
__device__ __align__(128) __half d_B1e[17 * 112 * 32];
__device__ __align__(128) __half d_B2e[17 * 32 * 112];
__device__ __align__(128) __half d_R1h[128 * 32];
__device__ __align__(128) __half d_R2h[64 * 112];
__device__ __align__(128) __half d_Y1r[(size_t)N_NODES * 128];
__device__ __align__(128) __half d_Y2r[(size_t)N_NODES * 64];
__device__ __align__(128) float  d_agg1[N_NODES * H1];   // self-cleaned by node1ew
__device__ __align__(128) float  d_agg2[N_NODES * H2];   // self-cleaned by node2pool
__device__ __align__(128) float  d_g   [N_GRAPHS * H2];  // self-cleaned by final
__device__ int   d_is64;

// ---------------- helpers -------------------------------------------------------
__device__ __forceinline__ void red_v4(float* p, float a, float b, float c, float d) {
    asm volatile("red.global.add.v4.f32 [%0], {%1,%2,%3,%4};"
                 :: "l"(p), "f"(a), "f"(b), "f"(c), "f"(d) : "memory");
}
__device__ __forceinline__ void red_v2(float* p, float a, float b) {
    asm volatile("red.global.add.v2.f32 [%0], {%1,%2};"
                 :: "l"(p), "f"(a), "f"(b) : "memory");
}
__device__ __forceinline__ int load_idx(const void* p, int i) {
    return d_is64 ? (int)((const long long*)p)[i] : ((const int*)p)[i];
}
__device__ __forceinline__ uint32_t smem_u32(const void* p) {
    uint32_t a;
    asm("{ .reg .u64 t; cvta.to.shared.u64 t, %1; cvt.u32.u64 %0, t; }"
        : "=r"(a) : "l"(p));
    return a;
}
__device__ __forceinline__ void ldsm_x4(uint32_t& r0, uint32_t& r1,
                                        uint32_t& r2, uint32_t& r3, uint32_t addr) {
    asm volatile("ldmatrix.sync.aligned.m8n8.x4.shared.b16 {%0,%1,%2,%3}, [%4];"
                 : "=r"(r0), "=r"(r1), "=r"(r2), "=r"(r3) : "r"(addr));
}
__device__ __forceinline__ void mma16816(float* c, const uint32_t* a,
                                         uint32_t b0, uint32_t b1) {
    asm volatile(
        "mma.sync.aligned.m16n8k16.row.col.f32.f16.f16.f32 "
        "{%0,%1,%2,%3}, {%4,%5,%6,%7}, {%8,%9}, {%0,%1,%2,%3};"
        : "+f"(c[0]), "+f"(c[1]), "+f"(c[2]), "+f"(c[3])
        : "r"(a[0]), "r"(a[1]), "r"(a[2]), "r"(a[3]), "r"(b0), "r"(b1));
}
__device__ __forceinline__ uint32_t hscale(uint32_t a, __half2 s) {
    __half2 av = *reinterpret_cast<__half2*>(&a);
    __half2 r  = __hmul2(av, s);
    return *reinterpret_cast<uint32_t*>(&r);
}

// ---------------- setup main: detect | xh | B1e | R1h ---------------------------
#define NB_XH   313
#define NB_B1E  238
#define NB_R1   16
#define NB_MAIN (1 + NB_XH + NB_B1E + NB_R1)

__global__ void __launch_bounds__(256) setup_main(
    const unsigned int* __restrict__ ei_words,
    const float* __restrict__ x,
    const float* __restrict__ W1, const float* __restrict__ b1,
    const float* __restrict__ root1)
{
    int blk = blockIdx.x;
    int tid = threadIdx.x;
    if (blk == 0) {
        __shared__ unsigned int red[256];
        unsigned int v = 0;
        for (int i = tid; i < N_EDGES; i += 256)
            v |= ei_words[2 * i + 1];
        red[tid] = v;
        __syncthreads();
        for (int s = 128; s > 0; s >>= 1) {
            if (tid < s) red[tid] |= red[tid + s];
            __syncthreads();
        }
        if (tid == 0) d_is64 = (red[0] == 0u) ? 1 : 0;
        return;
    }
    blk -= 1;
    if (blk < NB_XH) {
        int idx = blk * 256 + tid;
        if (idx < N_NODES * 4) {
            int n = idx >> 2, c8 = (idx & 3) * 8;
            float4 v0 = *(const float4*)&x[n * D_IN + c8];
            float4 v1 = *(const float4*)&x[n * D_IN + c8 + 4];
            __half2 h0 = __floats2half2_rn(v0.x, v0.y);
            __half2 h1 = __floats2half2_rn(v0.z, v0.w);
            __half2 h2 = __floats2half2_rn(v1.x, v1.y);
            __half2 h3 = __floats2half2_rn(v1.z, v1.w);
            uint4 u;
            u.x = *reinterpret_cast<unsigned int*>(&h0);
            u.y = *reinterpret_cast<unsigned int*>(&h1);
            u.z = *reinterpret_cast<unsigned int*>(&h2);
            u.w = *reinterpret_cast<unsigned int*>(&h3);
            *(uint4*)&d_xh[(size_t)n * D_IN + c8] = u;
        }
        return;
    }
    blk -= NB_XH;
    if (blk < NB_B1E) {
        int idx = blk * 256 + tid;
        int c = idx / 3584, rem = idx % 3584;
        int n = rem / 32, k = rem % 32;
        float v = 0.f;
        if (n < H1) {
            if (c < 16)      v = W1[c * (D_IN * H1) + k * H1 + n];
            else             v = b1[k * H1 + n];
        }
        d_B1e[idx] = __float2half(v);
        return;
    }
    blk -= NB_B1E;
    {
        int idx = blk * 256 + tid;
        int n = idx / 32, k = idx % 32;
        d_R1h[idx] = __float2half(n < H1 ? root1[k * H1 + n] : 0.f);
    }
}

// ---------------- setup aux (side stream): B2e | R2h -----------------------------
#define NB_B2E  238
#define NB_R2   28
#define NB_AUX  (NB_B2E + NB_R2)

__global__ void __launch_bounds__(256) setup_aux(
    const float* __restrict__ W2, const float* __restrict__ b2,
    const float* __restrict__ root2)
{
    int blk = blockIdx.x;
    int tid = threadIdx.x;
    if (blk < NB_B2E) {
        int idx = blk * 256 + tid;
        int c = idx / 3584, rem = idx % 3584;
        int n = rem / 112, k = rem % 112;
        float v = 0.f;
        if (n < H2 && k < H1) {
            if (c < 16)      v = W2[c * (H1 * H2) + k * H2 + n];
            else             v = b2[k * H2 + n];
        }
        d_B2e[idx] = __float2half(v);
        return;
    }
    blk -= NB_B2E;
    {
        int idx = blk * 256 + tid;
        int n = idx / 112, k = idx % 112;
        d_R2h[idx] = __float2half((n < H2 && k < H1) ? root2[k * H2 + n] : 0.f);
    }
}

// ---------------- mma.sync GEMM (proven R7) --------------------------------------
template<int KH, int BK>
__global__ void __launch_bounds__(128) gemm_mma(
    const __half* __restrict__ A, int M,
    const __half* __restrict__ B,
    __half* __restrict__ C, int Cstride)
{
    constexpr int PITCH = BK + 8;
    __shared__ __half As[128 * PITCH];
    __shared__ __half Bs[64 * PITCH];

    const int tid  = threadIdx.x;
    const int wid  = tid >> 5;
    const int lane = tid & 31;
    const int row0 = blockIdx.y * 128;
    const int col0 = blockIdx.x * 64;

    const uint32_t as_base = smem_u32(As);
    const uint32_t bs_base = smem_u32(Bs);

    float acc[2][8][4];
    #pragma unroll
    for (int mt = 0; mt < 2; mt++)
        #pragma unroll
        for (int nt = 0; nt < 8; nt++)
            #pragma unroll
            for (int q = 0; q < 4; q++) acc[mt][nt][q] = 0.f;

    const int l8 = lane & 7;
    const int mi = lane >> 3;

    for (int c0 = 0; c0 < KH; c0 += BK) {
        #pragma unroll
        for (int it = 0; it < (128 * BK / 8) / 128; it++) {
            int idx = it * 128 + tid;
            int r   = idx / (BK / 8);
            int i8  = (idx % (BK / 8)) * 8;
            int gr  = row0 + r;
            uint4 v = (gr < M) ? *(const uint4*)(A + (size_t)gr * KH + c0 + i8)
                               : make_uint4(0u, 0u, 0u, 0u);
            *(uint4*)(As + r * PITCH + i8) = v;
        }
        #pragma unroll
        for (int it = 0; it < (64 * BK / 8) / 128; it++) {
            int idx = it * 128 + tid;
            int r   = idx / (BK / 8);
            int i8  = (idx % (BK / 8)) * 8;
            uint4 v = *(const uint4*)(B + (size_t)(col0 + r) * KH + c0 + i8);
            *(uint4*)(Bs + r * PITCH + i8) = v;
        }
        __syncthreads();

        #pragma unroll
        for (int ks = 0; ks < BK / 16; ks++) {
            uint32_t a[2][4], b[4][4];
            #pragma unroll
            for (int mt = 0; mt < 2; mt++) {
                int row_l = wid * 32 + mt * 16 + l8 + (mi & 1) * 8;
                int kcol  = ks * 16 + (mi >> 1) * 8;
                ldsm_x4(a[mt][0], a[mt][1], a[mt][2], a[mt][3],
                        as_base + (row_l * PITCH + kcol) * 2);
            }
            #pragma unroll
            for (int p = 0; p < 4; p++) {
                int n_l  = p * 16 + l8 + (mi >> 1) * 8;
                int kcol = ks * 16 + (mi & 1) * 8;
                ldsm_x4(b[p][0], b[p][1], b[p][2], b[p][3],
                        bs_base + (n_l * PITCH + kcol) * 2);
            }
            #pragma unroll
            for (int mt = 0; mt < 2; mt++)
                #pragma unroll
                for (int nt = 0; nt < 8; nt++)
                    mma16816(acc[mt][nt], a[mt], b[nt >> 1][(nt & 1) * 2],
                             b[nt >> 1][(nt & 1) * 2 + 1]);
        }
        if (c0 + BK < KH) __syncthreads();
    }

    #pragma unroll
    for (int mt = 0; mt < 2; mt++) {
        int r_lo = row0 + wid * 32 + mt * 16 + (lane >> 2);
        int r_hi = r_lo + 8;
        #pragma unroll
        for (int nt = 0; nt < 8; nt++) {
            int col = col0 + nt * 8 + 2 * (lane & 3);
            __half2 lo = __floats2half2_rn(acc[mt][nt][0], acc[mt][nt][1]);
            __half2 hi = __floats2half2_rn(acc[mt][nt][2], acc[mt][nt][3]);
            if (r_lo < M) *(__half2*)(C + (size_t)r_lo * Cstride + col) = lo;
            if (r_hi < M) *(__half2*)(C + (size_t)r_hi * Cstride + col) = hi;
        }
    }
}

// ---------------- fused edge GEMM 1 (R8 verbatim) -------------------------------
__global__ void __launch_bounds__(256) edge_gemm1(
    const float* __restrict__ ea, const void* __restrict__ ei_raw)
{
    __shared__ __half xs[128 * 40];
    __shared__ __half Bs[112 * 40];
    __shared__ __half eas[128 * 17];
    __shared__ int srcs[128], dsts[128];

    const int tid  = threadIdx.x;
    const int w    = tid >> 5;
    const int lane = tid & 31;
    const int l8   = lane & 7;
    const int mi   = lane >> 3;
    const int e0   = blockIdx.x * 128;

    if (tid < 128) {
        int e = e0 + tid, ec = e < N_EDGES ? e : N_EDGES - 1;
        srcs[tid] = load_idx(ei_raw, ec);
        dsts[tid] = load_idx(ei_raw, N_EDGES + ec);
    }
    for (int idx = tid; idx < 128 * 17; idx += 256) {
        int r = idx / 17, c = idx - r * 17;
        int e = e0 + r, ec = e < N_EDGES ? e : N_EDGES - 1;
        eas[idx] = __float2half(c < 16 ? ea[ec * D_E + c] : 1.f);
    }
    __syncthreads();
    for (int idx = tid; idx < 128 * 4; idx += 256) {
        int r = idx >> 2, q = idx & 3;
        *(uint4*)(xs + r * 40 + q * 8) =
            *(const uint4*)(d_xh + (size_t)srcs[r] * D_IN + q * 8);
    }
    __syncthreads();

    uint32_t afr[2][4];
    {
        int row_l = w * 16 + l8 + (mi & 1) * 8;
        #pragma unroll
        for (int ks = 0; ks < 2; ks++)
            ldsm_x4(afr[ks][0], afr[ks][1], afr[ks][2], afr[ks][3],
                    smem_u32(xs) + (row_l * 40 + ks * 16 + (mi >> 1) * 8) * 2);
    }

    float acc[14][4];
    #pragma unroll
    for (int nt = 0; nt < 14; nt++)
        #pragma unroll
        for (int q = 0; q < 4; q++) acc[nt][q] = 0.f;

    const uint32_t bsb = smem_u32(Bs);
    const int rl0 = w * 16 + (lane >> 2);

    for (int c = 0; c < 17; c++) {
        __syncthreads();
        #pragma unroll
        for (int it = 0; it < 2; it++) {
            int idx = it * 256 + tid;
            if (idx < 448) {
                int n = idx >> 2, q = idx & 3;
                *(uint4*)(Bs + n * 40 + q * 8) =
                    *(const uint4*)(d_B1e + (c * 112 + n) * 32 + q * 8);
            }
        }
        __syncthreads();
        __half2 ca = __half2half2(eas[rl0 * 17 + c]);
        __half2 cb = __half2half2(eas[(rl0 + 8) * 17 + c]);
        #pragma unroll
        for (int ks = 0; ks < 2; ks++) {
            uint32_t sa[4];
            sa[0] = hscale(afr[ks][0], ca);
            sa[1] = hscale(afr[ks][1], cb);
            sa[2] = hscale(afr[ks][2], ca);
            sa[3] = hscale(afr[ks][3], cb);
            #pragma unroll
            for (int p = 0; p < 7; p++) {
                uint32_t b0, b1, b2, b3;
                int n_l = p * 16 + l8 + (mi >> 1) * 8;
                ldsm_x4(b0, b1, b2, b3,
                        bsb + (n_l * 40 + ks * 16 + (mi & 1) * 8) * 2);
                mma16816(acc[2 * p], sa, b0, b1);
                mma16816(acc[2 * p + 1], sa, b2, b3);
            }
        }
    }

    int dst0 = dsts[rl0], dst1 = dsts[rl0 + 8];
    bool v0 = (e0 + rl0) < N_EDGES, v1 = (e0 + rl0 + 8) < N_EDGES;
    #pragma unroll
    for (int nt = 0; nt < 13; nt++) {
        int col = nt * 8 + (lane & 3) * 2;
        if (col < H1) {
            if (v0) red_v2(d_agg1 + dst0 * H1 + col, acc[nt][0], acc[nt][1]);
            if (v1) red_v2(d_agg1 + dst1 * H1 + col, acc[nt][2], acc[nt][3]);
        }
    }
}

// ---------------- node update 1 (self-cleaning agg1) ------------------------------
__global__ void __launch_bounds__(256) node1ew(const float* __restrict__ bias1) {
    int idx = blockIdx.x * blockDim.x + threadIdx.x;
    if (idx >= N_NODES * 28) return;
    int n = idx / 28, c4 = (idx % 28) * 4;
    uint2 out;
    if (c4 < H1) {
        float4 a = *(const float4*)&d_agg1[n * H1 + c4];
        *(float4*)&d_agg1[n * H1 + c4] = make_float4(0.f, 0.f, 0.f, 0.f);
        uint2 u = *(const uint2*)&d_Y1r[(size_t)n * 128 + c4];
        __half2 h0 = *reinterpret_cast<__half2*>(&u.x);
        __half2 h1 = *reinterpret_cast<__half2*>(&u.y);
        float2 r0 = __half22float2(h0), r1 = __half22float2(h1);
        float4 b = *(const float4*)&bias1[c4];
        __half2 o0 = __floats2half2_rn(fmaxf(a.x + r0.x + b.x, 0.f),
                                       fmaxf(a.y + r0.y + b.y, 0.f));
        __half2 o1 = __floats2half2_rn(fmaxf(a.z + r1.x + b.z, 0.f),
                                       fmaxf(a.w + r1.y + b.w, 0.f));
        out.x = *reinterpret_cast<unsigned int*>(&o0);
        out.y = *reinterpret_cast<unsigned int*>(&o1);
    } else {
        out.x = 0u; out.y = 0u;
    }
    *(uint2*)&d_h1h[(size_t)n * H1P + c4] = out;
}

// ---------------- fused edge GEMM 2 (R8 verbatim) ---------------------------------
__global__ void __launch_bounds__(256) edge_gemm2(
    const float* __restrict__ ea, const void* __restrict__ ei_raw)
{
    __shared__ __half hs[128 * 120];
    __shared__ __half Bs[32 * 120];
    __shared__ __half eas[128 * 17];
    __shared__ int srcs[128], dsts[128];

    const int tid  = threadIdx.x;
    const int w    = tid >> 5;
    const int lane = tid & 31;
    const int l8   = lane & 7;
    const int mi   = lane >> 3;
    const int e0   = blockIdx.x * 128;

    if (tid < 128) {
        int e = e0 + tid, ec = e < N_EDGES ? e : N_EDGES - 1;
        srcs[tid] = load_idx(ei_raw, ec);
        dsts[tid] = load_idx(ei_raw, N_EDGES + ec);
    }
    for (int idx = tid; idx < 128 * 17; idx += 256) {
        int r = idx / 17, c = idx - r * 17;
        int e = e0 + r, ec = e < N_EDGES ? e : N_EDGES - 1;
        eas[idx] = __float2half(c < 16 ? ea[ec * D_E + c] : 1.f);
    }
    __syncthreads();
    for (int idx = tid; idx < 128 * 14; idx += 256) {
        int r = idx / 14, q = idx % 14;
        *(uint4*)(hs + r * 120 + q * 8) =
            *(const uint4*)(d_h1h + (size_t)srcs[r] * H1P + q * 8);
    }
    __syncthreads();

    uint32_t afr[7][4];
    {
        int row_l = w * 16 + l8 + (mi & 1) * 8;
        #pragma unroll
        for (int ks = 0; ks < 7; ks++)
            ldsm_x4(afr[ks][0], afr[ks][1], afr[ks][2], afr[ks][3],
                    smem_u32(hs) + (row_l * 120 + ks * 16 + (mi >> 1) * 8) * 2);
    }

    float acc[3][4];
    #pragma unroll
    for (int nt = 0; nt < 3; nt++)
        #pragma unroll
        for (int q = 0; q < 4; q++) acc[nt][q] = 0.f;

    const uint32_t bsb = smem_u32(Bs);
    const int rl0 = w * 16 + (lane >> 2);

    for (int c = 0; c < 17; c++) {
        __syncthreads();
        for (int idx = tid; idx < 448; idx += 256) {
            int n = idx / 14, q = idx % 14;
            *(uint4*)(Bs + n * 120 + q * 8) =
                *(const uint4*)(d_B2e + (c * 32 + n) * 112 + q * 8);
        }
        __syncthreads();
        __half2 ca = __half2half2(eas[rl0 * 17 + c]);
        __half2 cb = __half2half2(eas[(rl0 + 8) * 17 + c]);
        #pragma unroll
        for (int ks = 0; ks < 7; ks++) {
            uint32_t sa[4];
            sa[0] = hscale(afr[ks][0], ca);
            sa[1] = hscale(afr[ks][1], cb);
            sa[2] = hscale(afr[ks][2], ca);
            sa[3] = hscale(afr[ks][3], cb);
            uint32_t b0, b1, b2, b3;
            int kcol = ks * 16 + (mi & 1) * 8;
            ldsm_x4(b0, b1, b2, b3, bsb + ((l8 + (mi >> 1) * 8) * 120 + kcol) * 2);
            mma16816(acc[0], sa, b0, b1);
            mma16816(acc[1], sa, b2, b3);
            ldsm_x4(b0, b1, b2, b3, bsb + ((16 + l8 + (mi >> 1) * 8) * 120 + kcol) * 2);
            mma16816(acc[2], sa, b0, b1);
        }
    }

    int dst0 = dsts[rl0], dst1 = dsts[rl0 + 8];
    bool v0 = (e0 + rl0) < N_EDGES, v1 = (e0 + rl0 + 8) < N_EDGES;
    #pragma unroll
    for (int nt = 0; nt < 3; nt++) {
        int col = nt * 8 + (lane & 3) * 2;
        if (col < H2) {
            if (v0) red_v2(d_agg2 + dst0 * H2 + col, acc[nt][0], acc[nt][1]);
            if (v1) red_v2(d_agg2 + dst1 * H2 + col, acc[nt][2], acc[nt][3]);
        }
    }
}

// ---------------- node update 2 + sum-pool (self-cleaning agg2) --------------------
__global__ void __launch_bounds__(256) node2pool(
    const float* __restrict__ bias2, const void* __restrict__ batch_raw)
{
    int idx = blockIdx.x * blockDim.x + threadIdx.x;
    if (idx >= N_NODES * 5) return;
    int n = idx / 5, c4 = (idx % 5) * 4;
    float4 a = *(const float4*)&d_agg2[n * H2 + c4];
    *(float4*)&d_agg2[n * H2 + c4] = make_float4(0.f, 0.f, 0.f, 0.f);
    uint2 u = *(const uint2*)&d_Y2r[(size_t)n * 64 + c4];
    __half2 h0 = *reinterpret_cast<__half2*>(&u.x);
    __half2 h1 = *reinterpret_cast<__half2*>(&u.y);
    float2 y0 = __half22float2(h0), y1 = __half22float2(h1);
    float4 b = *(const float4*)&bias2[c4];
    float v0 = fmaxf(a.x + y0.x + b.x, 0.f);
    float v1 = fmaxf(a.y + y0.y + b.y, 0.f);
    float v2 = fmaxf(a.z + y1.x + b.z, 0.f);
    float v3 = fmaxf(a.w + y1.y + b.w, 0.f);
    int g = load_idx(batch_raw, n);
    red_v4(d_g + g * H2 + c4, v0, v1, v2, v3);
}

// ---------------- fused FCN head (self-cleaning d_g) --------------------------------
__global__ void __launch_bounds__(64) final_kernel(
    const float* __restrict__ lin1_W, const float* __restrict__ lin1_b,
    const float* __restrict__ lin2_W, const float* __restrict__ lin2_b,
    float* __restrict__ out)
{
    __shared__ float g1s[F1];
    int gi  = blockIdx.x;
    int tid = threadIdx.x;
    if (tid < F1) {
        float acc = lin1_b[tid];
        #pragma unroll
        for (int i = 0; i < H2; ++i)
            acc = fmaf(d_g[gi * H2 + i], lin1_W[i * F1 + tid], acc);
        g1s[tid] = fmaxf(acc, 0.f);
    }
    __syncthreads();
    if (tid < H2) d_g[gi * H2 + tid] = 0.f;   // clean for next call
    if (tid < 32) {
        float v = 0.f;
        #pragma unroll
        for (int j = tid; j < F1; j += 32)
            v = fmaf(g1s[j], lin2_W[j], v);
        #pragma unroll
        for (int s = 16; s > 0; s >>= 1)
            v += __shfl_down_sync(0xffffffffu, v, s);
        if (tid == 0) out[gi] = v + lin2_b[0];
    }
}

// ---------------- launch: fork/join + split setup -----------------------------------
extern "C" void kernel_launch(void* const* d_in, const int* in_sizes, int n_in,
                              void* d_out, int out_size)
{
    const float* x      = (const float*)d_in[0];
    const float* ea     = (const float*)d_in[1];
    const void*  ei     = d_in[2];
    const void*  batch  = d_in[3];
    const float* nn1_W  = (const float*)d_in[4];
    const float* nn1_b  = (const float*)d_in[5];
    const float* root1  = (const float*)d_in[6];
    const float* bias1  = (const float*)d_in[7];
    const float* nn2_W  = (const float*)d_in[8];
    const float* nn2_b  = (const float*)d_in[9];
    const float* root2  = (const float*)d_in[10];
    const float* bias2  = (const float*)d_in[11];
    const float* lin1_W = (const float*)d_in[12];
    const float* lin1_b = (const float*)d_in[13];
    const float* lin2_W = (const float*)d_in[14];
    const float* lin2_b = (const float*)d_in[15];
    float* out = (float*)d_out;

    __half *xh, *h1h, *R1h, *R2h, *Y1r, *Y2r;
    cudaGetSymbolAddress((void**)&xh,  d_xh);
    cudaGetSymbolAddress((void**)&h1h, d_h1h);
    cudaGetSymbolAddress((void**)&R1h, d_R1h);
    cudaGetSymbolAddress((void**)&R2h, d_R2h);
    cudaGetSymbolAddress((void**)&Y1r, d_Y1r);
    cudaGetSymbolAddress((void**)&Y2r, d_Y2r);

    cudaStream_t s1;
    cudaStreamCreateWithFlags(&s1, cudaStreamNonBlocking);
    cudaEvent_t eFork0, eFork1, eJoin1, eFork2, eJoin2;
    cudaEventCreateWithFlags(&eFork0, cudaEventDisableTiming);
    cudaEventCreateWithFlags(&eFork1, cudaEventDisableTiming);
    cudaEventCreateWithFlags(&eJoin1, cudaEventDisableTiming);
    cudaEventCreateWithFlags(&eFork2, cudaEventDisableTiming);
    cudaEventCreateWithFlags(&eJoin2, cudaEventDisableTiming);

    // fork at entry: aux setup (layer-2 weights) runs beside everything layer-1
    cudaEventRecord(eFork0, 0);
    cudaStreamWaitEvent(s1, eFork0, 0);
    setup_aux<<<NB_AUX, 256, 0, s1>>>(nn2_W, nn2_b, root2);

    setup_main<<<NB_MAIN, 256>>>((const unsigned int*)ei, x, nn1_W, nn1_b, root1);

    // fork: root GEMM 1 on s1 (after setup_main), edge GEMM 1 on main
    cudaEventRecord(eFork1, 0);
    cudaStreamWaitEvent(s1, eFork1, 0);
    gemm_mma<32, 32><<<dim3(2, 157), 128, 0, s1>>>(xh, N_NODES, R1h, Y1r, 128);
    cudaEventRecord(eJoin1, s1);

    edge_gemm1<<<(N_EDGES + 127) / 128, 256>>>(ea, ei);
    cudaStreamWaitEvent(0, eJoin1, 0);
    node1ew<<<(N_NODES * 28 + 255) / 256, 256>>>(bias1);

    // fork: root GEMM 2 on s1, edge GEMM 2 on main
    cudaEventRecord(eFork2, 0);
    cudaStreamWaitEvent(s1, eFork2, 0);
    gemm_mma<112, 112><<<dim3(1, 157), 128, 0, s1>>>(h1h, N_NODES, R2h, Y2r, 64);
    cudaEventRecord(eJoin2, s1);

    edge_gemm2<<<(N_EDGES + 127) / 128, 256>>>(ea, ei);
    cudaStreamWaitEvent(0, eJoin2, 0);
    node2pool<<<(N_NODES * 5 + 255) / 256, 256>>>(bias2, batch);

    final_kernel<<<N_GRAPHS, 64>>>(lin1_W, lin1_b, lin2_W, lin2_b, out);
}

// round 17
// speedup vs baseline: 1.1694x; 1.1694x over previous
#include <cuda_runtime.h>
#include <cuda_fp16.h>
#include <cstdint>

#define N_NODES  20000
#define N_EDGES  40000
#define N_GRAPHS 500
#define D_IN     32
#define D_E      16
#define H1       100
#define H2       20
#define F1       50
#define H1P      112

// ---------------- scratch -----------------------------------------------------
__device__ __align__(128) __half d_xh [(size_t)N_NODES * D_IN];
__device__ __align__(128) __half d_h1h[(size_t)N_NODES * H1P];
__device__ __align__(128) __half d_B1e[17 * 112 * 32];
__device__ __align__(128) __half d_B2e[17 * 32 * 112];
__device__ __align__(128) __half d_R1h[128 * 32];
__device__ __align__(128) __half d_R2h[64 * 112];
__device__ __align__(128) __half d_Y1r[(size_t)N_NODES * 128];
__device__ __align__(128) __half d_Y2r[(size_t)N_NODES * 64];
__device__ __align__(128) float  d_agg1[N_NODES * H1];
__device__ __align__(128) float  d_agg2[N_NODES * H2];
__device__ __align__(128) float  d_g   [N_GRAPHS * H2];
__device__ int   d_is64;

// ---------------- helpers -------------------------------------------------------
__device__ __forceinline__ void red_v4(float* p, float a, float b, float c, float d) {
    asm volatile("red.global.add.v4.f32 [%0], {%1,%2,%3,%4};"
                 :: "l"(p), "f"(a), "f"(b), "f"(c), "f"(d) : "memory");
}
__device__ __forceinline__ void red_v2(float* p, float a, float b) {
    asm volatile("red.global.add.v2.f32 [%0], {%1,%2};"
                 :: "l"(p), "f"(a), "f"(b) : "memory");
}
__device__ __forceinline__ int load_idx(const void* p, int i) {
    return d_is64 ? (int)((const long long*)p)[i] : ((const int*)p)[i];
}
__device__ __forceinline__ uint32_t smem_u32(const void* p) {
    uint32_t a;
    asm("{ .reg .u64 t; cvta.to.shared.u64 t, %1; cvt.u32.u64 %0, t; }"
        : "=r"(a) : "l"(p));
    return a;
}
__device__ __forceinline__ void ldsm_x4(uint32_t& r0, uint32_t& r1,
                                        uint32_t& r2, uint32_t& r3, uint32_t addr) {
    asm volatile("ldmatrix.sync.aligned.m8n8.x4.shared.b16 {%0,%1,%2,%3}, [%4];"
                 : "=r"(r0), "=r"(r1), "=r"(r2), "=r"(r3) : "r"(addr));
}
__device__ __forceinline__ void mma16816(float* c, const uint32_t* a,
                                         uint32_t b0, uint32_t b1) {
    asm volatile(
        "mma.sync.aligned.m16n8k16.row.col.f32.f16.f16.f32 "
        "{%0,%1,%2,%3}, {%4,%5,%6,%7}, {%8,%9}, {%0,%1,%2,%3};"
        : "+f"(c[0]), "+f"(c[1]), "+f"(c[2]), "+f"(c[3])
        : "r"(a[0]), "r"(a[1]), "r"(a[2]), "r"(a[3]), "r"(b0), "r"(b1));
}
__device__ __forceinline__ uint32_t hscale(uint32_t a, __half2 s) {
    __half2 av = *reinterpret_cast<__half2*>(&a);
    __half2 r  = __hmul2(av, s);
    return *reinterpret_cast<uint32_t*>(&r);
}

// ---------------- fused setup (R15 verbatim) --------------------------------------
#define NB_XH   313
#define NB_B1E  238
#define NB_B2E  238
#define NB_R1   16
#define NB_R2   28
#define Z4_A1 (N_NODES * H1 / 4)
#define Z4_A2 (Z4_A1 + N_NODES * H2 / 4)
#define Z4_G  (Z4_A2 + N_GRAPHS * H2 / 4)
#define NB_ZERO ((Z4_G + 255) / 256)
#define NB_SETUP (1 + NB_XH + NB_B1E + NB_B2E + NB_R1 + NB_R2 + NB_ZERO)

__global__ void __launch_bounds__(256) setup_kernel(
    const unsigned int* __restrict__ ei_words,
    const float* __restrict__ x,
    const float* __restrict__ W1, const float* __restrict__ b1,
    const float* __restrict__ root1,
    const float* __restrict__ W2, const float* __restrict__ b2,
    const float* __restrict__ root2)
{
    int blk = blockIdx.x;
    int tid = threadIdx.x;
    if (blk == 0) {
        __shared__ unsigned int red[256];
        unsigned int v = 0;
        for (int i = tid; i < N_EDGES; i += 256)
            v |= ei_words[2 * i + 1];
        red[tid] = v;
        __syncthreads();
        for (int s = 128; s > 0; s >>= 1) {
            if (tid < s) red[tid] |= red[tid + s];
            __syncthreads();
        }
        if (tid == 0) d_is64 = (red[0] == 0u) ? 1 : 0;
        return;
    }
    blk -= 1;
    if (blk < NB_XH) {
        int idx = blk * 256 + tid;
        if (idx < N_NODES * 4) {
            int n = idx >> 2, c8 = (idx & 3) * 8;
            float4 v0 = *(const float4*)&x[n * D_IN + c8];
            float4 v1 = *(const float4*)&x[n * D_IN + c8 + 4];
            __half2 h0 = __floats2half2_rn(v0.x, v0.y);
            __half2 h1 = __floats2half2_rn(v0.z, v0.w);
            __half2 h2 = __floats2half2_rn(v1.x, v1.y);
            __half2 h3 = __floats2half2_rn(v1.z, v1.w);
            uint4 u;
            u.x = *reinterpret_cast<unsigned int*>(&h0);
            u.y = *reinterpret_cast<unsigned int*>(&h1);
            u.z = *reinterpret_cast<unsigned int*>(&h2);
            u.w = *reinterpret_cast<unsigned int*>(&h3);
            *(uint4*)&d_xh[(size_t)n * D_IN + c8] = u;
        }
        return;
    }
    blk -= NB_XH;
    if (blk < NB_B1E) {
        int idx = blk * 256 + tid;
        int c = idx / 3584, rem = idx % 3584;
        int n = rem / 32, k = rem % 32;
        float v = 0.f;
        if (n < H1) {
            if (c < 16)      v = W1[c * (D_IN * H1) + k * H1 + n];
            else             v = b1[k * H1 + n];
        }
        d_B1e[idx] = __float2half(v);
        return;
    }
    blk -= NB_B1E;
    if (blk < NB_B2E) {
        int idx = blk * 256 + tid;
        int c = idx / 3584, rem = idx % 3584;
        int n = rem / 112, k = rem % 112;
        float v = 0.f;
        if (n < H2 && k < H1) {
            if (c < 16)      v = W2[c * (H1 * H2) + k * H2 + n];
            else             v = b2[k * H2 + n];
        }
        d_B2e[idx] = __float2half(v);
        return;
    }
    blk -= NB_B2E;
    if (blk < NB_R1) {
        int idx = blk * 256 + tid;
        int n = idx / 32, k = idx % 32;
        d_R1h[idx] = __float2half(n < H1 ? root1[k * H1 + n] : 0.f);
        return;
    }
    blk -= NB_R1;
    if (blk < NB_R2) {
        int idx = blk * 256 + tid;
        int n = idx / 112, k = idx % 112;
        d_R2h[idx] = __float2half((n < H2 && k < H1) ? root2[k * H2 + n] : 0.f);
        return;
    }
    blk -= NB_R2;
    {
        int i = blk * 256 + tid;
        float4 z = make_float4(0.f, 0.f, 0.f, 0.f);
        if (i < Z4_A1) ((float4*)d_agg1)[i] = z;
        else if (i < Z4_A2) ((float4*)d_agg2)[i - Z4_A1] = z;
        else if (i < Z4_G)  ((float4*)d_g)[i - Z4_A2] = z;
    }
}

// ---------------- mma.sync GEMM (proven R7) --------------------------------------
template<int KH, int BK>
__global__ void __launch_bounds__(128) gemm_mma(
    const __half* __restrict__ A, int M,
    const __half* __restrict__ B,
    __half* __restrict__ C, int Cstride)
{
    constexpr int PITCH = BK + 8;
    __shared__ __half As[128 * PITCH];
    __shared__ __half Bs[64 * PITCH];

    const int tid  = threadIdx.x;
    const int wid  = tid >> 5;
    const int lane = tid & 31;
    const int row0 = blockIdx.y * 128;
    const int col0 = blockIdx.x * 64;

    const uint32_t as_base = smem_u32(As);
    const uint32_t bs_base = smem_u32(Bs);

    float acc[2][8][4];
    #pragma unroll
    for (int mt = 0; mt < 2; mt++)
        #pragma unroll
        for (int nt = 0; nt < 8; nt++)
            #pragma unroll
            for (int q = 0; q < 4; q++) acc[mt][nt][q] = 0.f;

    const int l8 = lane & 7;
    const int mi = lane >> 3;

    for (int c0 = 0; c0 < KH; c0 += BK) {
        #pragma unroll
        for (int it = 0; it < (128 * BK / 8) / 128; it++) {
            int idx = it * 128 + tid;
            int r   = idx / (BK / 8);
            int i8  = (idx % (BK / 8)) * 8;
            int gr  = row0 + r;
            uint4 v = (gr < M) ? *(const uint4*)(A + (size_t)gr * KH + c0 + i8)
                               : make_uint4(0u, 0u, 0u, 0u);
            *(uint4*)(As + r * PITCH + i8) = v;
        }
        #pragma unroll
        for (int it = 0; it < (64 * BK / 8) / 128; it++) {
            int idx = it * 128 + tid;
            int r   = idx / (BK / 8);
            int i8  = (idx % (BK / 8)) * 8;
            uint4 v = *(const uint4*)(B + (size_t)(col0 + r) * KH + c0 + i8);
            *(uint4*)(Bs + r * PITCH + i8) = v;
        }
        __syncthreads();

        #pragma unroll
        for (int ks = 0; ks < BK / 16; ks++) {
            uint32_t a[2][4], b[4][4];
            #pragma unroll
            for (int mt = 0; mt < 2; mt++) {
                int row_l = wid * 32 + mt * 16 + l8 + (mi & 1) * 8;
                int kcol  = ks * 16 + (mi >> 1) * 8;
                ldsm_x4(a[mt][0], a[mt][1], a[mt][2], a[mt][3],
                        as_base + (row_l * PITCH + kcol) * 2);
            }
            #pragma unroll
            for (int p = 0; p < 4; p++) {
                int n_l  = p * 16 + l8 + (mi >> 1) * 8;
                int kcol = ks * 16 + (mi & 1) * 8;
                ldsm_x4(b[p][0], b[p][1], b[p][2], b[p][3],
                        bs_base + (n_l * PITCH + kcol) * 2);
            }
            #pragma unroll
            for (int mt = 0; mt < 2; mt++)
                #pragma unroll
                for (int nt = 0; nt < 8; nt++)
                    mma16816(acc[mt][nt], a[mt], b[nt >> 1][(nt & 1) * 2],
                             b[nt >> 1][(nt & 1) * 2 + 1]);
        }
        if (c0 + BK < KH) __syncthreads();
    }

    #pragma unroll
    for (int mt = 0; mt < 2; mt++) {
        int r_lo = row0 + wid * 32 + mt * 16 + (lane >> 2);
        int r_hi = r_lo + 8;
        #pragma unroll
        for (int nt = 0; nt < 8; nt++) {
            int col = col0 + nt * 8 + 2 * (lane & 3);
            __half2 lo = __floats2half2_rn(acc[mt][nt][0], acc[mt][nt][1]);
            __half2 hi = __floats2half2_rn(acc[mt][nt][2], acc[mt][nt][3]);
            if (r_lo < M) *(__half2*)(C + (size_t)r_lo * Cstride + col) = lo;
            if (r_hi < M) *(__half2*)(C + (size_t)r_hi * Cstride + col) = hi;
        }
    }
}

// ---------------- edge GEMM 1, N-split: tiles [T0, T0+NT) of 7 --------------------
// 128 edges/block, 256 threads. Per-block acc = 2*NT n8-tiles.
template<int T0, int NT>
__global__ void __launch_bounds__(256) edge_gemm1p(
    const float* __restrict__ ea, const void* __restrict__ ei_raw)
{
    __shared__ __half xs[128 * 40];
    __shared__ __half Bs[NT * 16 * 40];
    __shared__ __half eas[128 * 17];
    __shared__ int srcs[128], dsts[128];

    const int tid  = threadIdx.x;
    const int w    = tid >> 5;
    const int lane = tid & 31;
    const int l8   = lane & 7;
    const int mi   = lane >> 3;
    const int e0   = blockIdx.x * 128;

    if (tid < 128) {
        int e = e0 + tid, ec = e < N_EDGES ? e : N_EDGES - 1;
        srcs[tid] = load_idx(ei_raw, ec);
        dsts[tid] = load_idx(ei_raw, N_EDGES + ec);
    }
    for (int idx = tid; idx < 128 * 17; idx += 256) {
        int r = idx / 17, c = idx - r * 17;
        int e = e0 + r, ec = e < N_EDGES ? e : N_EDGES - 1;
        eas[idx] = __float2half(c < 16 ? ea[ec * D_E + c] : 1.f);
    }
    __syncthreads();
    for (int idx = tid; idx < 128 * 4; idx += 256) {
        int r = idx >> 2, q = idx & 3;
        *(uint4*)(xs + r * 40 + q * 8) =
            *(const uint4*)(d_xh + (size_t)srcs[r] * D_IN + q * 8);
    }
    __syncthreads();

    uint32_t afr[2][4];
    {
        int row_l = w * 16 + l8 + (mi & 1) * 8;
        #pragma unroll
        for (int ks = 0; ks < 2; ks++)
            ldsm_x4(afr[ks][0], afr[ks][1], afr[ks][2], afr[ks][3],
                    smem_u32(xs) + (row_l * 40 + ks * 16 + (mi >> 1) * 8) * 2);
    }

    float acc[2 * NT][4];
    #pragma unroll
    for (int nt = 0; nt < 2 * NT; nt++)
        #pragma unroll
        for (int q = 0; q < 4; q++) acc[nt][q] = 0.f;

    const uint32_t bsb = smem_u32(Bs);
    const int rl0 = w * 16 + (lane >> 2);

    for (int c = 0; c < 17; c++) {
        __syncthreads();
        // stage this coeff's rows [T0*16, T0*16 + NT*16), pitch 40
        {
            int idx = tid;
            if (idx < NT * 64) {
                int n = idx >> 2, q = idx & 3;
                *(uint4*)(Bs + n * 40 + q * 8) =
                    *(const uint4*)(d_B1e + (c * 112 + T0 * 16 + n) * 32 + q * 8);
            }
        }
        __syncthreads();
        __half2 ca = __half2half2(eas[rl0 * 17 + c]);
        __half2 cb = __half2half2(eas[(rl0 + 8) * 17 + c]);
        #pragma unroll
        for (int ks = 0; ks < 2; ks++) {
            uint32_t sa[4];
            sa[0] = hscale(afr[ks][0], ca);
            sa[1] = hscale(afr[ks][1], cb);
            sa[2] = hscale(afr[ks][2], ca);
            sa[3] = hscale(afr[ks][3], cb);
            #pragma unroll
            for (int p = 0; p < NT; p++) {
                uint32_t b0, b1, b2, b3;
                int n_l = p * 16 + l8 + (mi >> 1) * 8;
                ldsm_x4(b0, b1, b2, b3,
                        bsb + (n_l * 40 + ks * 16 + (mi & 1) * 8) * 2);
                mma16816(acc[2 * p], sa, b0, b1);
                mma16816(acc[2 * p + 1], sa, b2, b3);
            }
        }
    }

    int dst0 = dsts[rl0], dst1 = dsts[rl0 + 8];
    bool v0 = (e0 + rl0) < N_EDGES, v1 = (e0 + rl0 + 8) < N_EDGES;
    #pragma unroll
    for (int nt = 0; nt < 2 * NT; nt++) {
        int col = (T0 * 2 + nt) * 8 + (lane & 3) * 2;
        if (col < H1) {
            if (v0) red_v2(d_agg1 + dst0 * H1 + col, acc[nt][0], acc[nt][1]);
            if (v1) red_v2(d_agg1 + dst1 * H1 + col, acc[nt][2], acc[nt][3]);
        }
    }
}

// ---------------- node update 1 (R15 verbatim) ------------------------------------
__global__ void __launch_bounds__(256) node1ew(const float* __restrict__ bias1) {
    int idx = blockIdx.x * blockDim.x + threadIdx.x;
    if (idx >= N_NODES * 28) return;
    int n = idx / 28, c4 = (idx % 28) * 4;
    uint2 out;
    if (c4 < H1) {
        float4 a = *(const float4*)&d_agg1[n * H1 + c4];
        uint2 u = *(const uint2*)&d_Y1r[(size_t)n * 128 + c4];
        __half2 h0 = *reinterpret_cast<__half2*>(&u.x);
        __half2 h1 = *reinterpret_cast<__half2*>(&u.y);
        float2 r0 = __half22float2(h0), r1 = __half22float2(h1);
        float4 b = *(const float4*)&bias1[c4];
        __half2 o0 = __floats2half2_rn(fmaxf(a.x + r0.x + b.x, 0.f),
                                       fmaxf(a.y + r0.y + b.y, 0.f));
        __half2 o1 = __floats2half2_rn(fmaxf(a.z + r1.x + b.z, 0.f),
                                       fmaxf(a.w + r1.y + b.w, 0.f));
        out.x = *reinterpret_cast<unsigned int*>(&o0);
        out.y = *reinterpret_cast<unsigned int*>(&o1);
    } else {
        out.x = 0u; out.y = 0u;
    }
    *(uint2*)&d_h1h[(size_t)n * H1P + c4] = out;
}

// ---------------- fused edge GEMM 2 (R15 verbatim) ---------------------------------
__global__ void __launch_bounds__(256) edge_gemm2(
    const float* __restrict__ ea, const void* __restrict__ ei_raw)
{
    __shared__ __half hs[128 * 120];
    __shared__ __half Bs[32 * 120];
    __shared__ __half eas[128 * 17];
    __shared__ int srcs[128], dsts[128];

    const int tid  = threadIdx.x;
    const int w    = tid >> 5;
    const int lane = tid & 31;
    const int l8   = lane & 7;
    const int mi   = lane >> 3;
    const int e0   = blockIdx.x * 128;

    if (tid < 128) {
        int e = e0 + tid, ec = e < N_EDGES ? e : N_EDGES - 1;
        srcs[tid] = load_idx(ei_raw, ec);
        dsts[tid] = load_idx(ei_raw, N_EDGES + ec);
    }
    for (int idx = tid; idx < 128 * 17; idx += 256) {
        int r = idx / 17, c = idx - r * 17;
        int e = e0 + r, ec = e < N_EDGES ? e : N_EDGES - 1;
        eas[idx] = __float2half(c < 16 ? ea[ec * D_E + c] : 1.f);
    }
    __syncthreads();
    for (int idx = tid; idx < 128 * 14; idx += 256) {
        int r = idx / 14, q = idx % 14;
        *(uint4*)(hs + r * 120 + q * 8) =
            *(const uint4*)(d_h1h + (size_t)srcs[r] * H1P + q * 8);
    }
    __syncthreads();

    uint32_t afr[7][4];
    {
        int row_l = w * 16 + l8 + (mi & 1) * 8;
        #pragma unroll
        for (int ks = 0; ks < 7; ks++)
            ldsm_x4(afr[ks][0], afr[ks][1], afr[ks][2], afr[ks][3],
                    smem_u32(hs) + (row_l * 120 + ks * 16 + (mi >> 1) * 8) * 2);
    }

    float acc[3][4];
    #pragma unroll
    for (int nt = 0; nt < 3; nt++)
        #pragma unroll
        for (int q = 0; q < 4; q++) acc[nt][q] = 0.f;

    const uint32_t bsb = smem_u32(Bs);
    const int rl0 = w * 16 + (lane >> 2);

    for (int c = 0; c < 17; c++) {
        __syncthreads();
        for (int idx = tid; idx < 448; idx += 256) {
            int n = idx / 14, q = idx % 14;
            *(uint4*)(Bs + n * 120 + q * 8) =
                *(const uint4*)(d_B2e + (c * 32 + n) * 112 + q * 8);
        }
        __syncthreads();
        __half2 ca = __half2half2(eas[rl0 * 17 + c]);
        __half2 cb = __half2half2(eas[(rl0 + 8) * 17 + c]);
        #pragma unroll
        for (int ks = 0; ks < 7; ks++) {
            uint32_t sa[4];
            sa[0] = hscale(afr[ks][0], ca);
            sa[1] = hscale(afr[ks][1], cb);
            sa[2] = hscale(afr[ks][2], ca);
            sa[3] = hscale(afr[ks][3], cb);
            uint32_t b0, b1, b2, b3;
            int kcol = ks * 16 + (mi & 1) * 8;
            ldsm_x4(b0, b1, b2, b3, bsb + ((l8 + (mi >> 1) * 8) * 120 + kcol) * 2);
            mma16816(acc[0], sa, b0, b1);
            mma16816(acc[1], sa, b2, b3);
            ldsm_x4(b0, b1, b2, b3, bsb + ((16 + l8 + (mi >> 1) * 8) * 120 + kcol) * 2);
            mma16816(acc[2], sa, b0, b1);
        }
    }

    int dst0 = dsts[rl0], dst1 = dsts[rl0 + 8];
    bool v0 = (e0 + rl0) < N_EDGES, v1 = (e0 + rl0 + 8) < N_EDGES;
    #pragma unroll
    for (int nt = 0; nt < 3; nt++) {
        int col = nt * 8 + (lane & 3) * 2;
        if (col < H2) {
            if (v0) red_v2(d_agg2 + dst0 * H2 + col, acc[nt][0], acc[nt][1]);
            if (v1) red_v2(d_agg2 + dst1 * H2 + col, acc[nt][2], acc[nt][3]);
        }
    }
}

// ---------------- node update 2 + sum-pool (R15 verbatim) ---------------------------
__global__ void __launch_bounds__(256) node2pool(
    const float* __restrict__ bias2, const void* __restrict__ batch_raw)
{
    int idx = blockIdx.x * blockDim.x + threadIdx.x;
    if (idx >= N_NODES * 5) return;
    int n = idx / 5, c4 = (idx % 5) * 4;
    float4 a = *(const float4*)&d_agg2[n * H2 + c4];
    uint2 u = *(const uint2*)&d_Y2r[(size_t)n * 64 + c4];
    __half2 h0 = *reinterpret_cast<__half2*>(&u.x);
    __half2 h1 = *reinterpret_cast<__half2*>(&u.y);
    float2 y0 = __half22float2(h0), y1 = __half22float2(h1);
    float4 b = *(const float4*)&bias2[c4];
    float v0 = fmaxf(a.x + y0.x + b.x, 0.f);
    float v1 = fmaxf(a.y + y0.y + b.y, 0.f);
    float v2 = fmaxf(a.z + y1.x + b.z, 0.f);
    float v3 = fmaxf(a.w + y1.y + b.w, 0.f);
    int g = load_idx(batch_raw, n);
    red_v4(d_g + g * H2 + c4, v0, v1, v2, v3);
}

// ---------------- fused FCN head (R15 verbatim) --------------------------------------
__global__ void __launch_bounds__(64) final_kernel(
    const float* __restrict__ lin1_W, const float* __restrict__ lin1_b,
    const float* __restrict__ lin2_W, const float* __restrict__ lin2_b,
    float* __restrict__ out)
{
    __shared__ float g1s[F1];
    int gi  = blockIdx.x;
    int tid = threadIdx.x;
    if (tid < F1) {
        float acc = lin1_b[tid];
        #pragma unroll
        for (int i = 0; i < H2; ++i)
            acc = fmaf(d_g[gi * H2 + i], lin1_W[i * F1 + tid], acc);
        g1s[tid] = fmaxf(acc, 0.f);
    }
    __syncthreads();
    if (tid < 32) {
        float v = 0.f;
        #pragma unroll
        for (int j = tid; j < F1; j += 32)
            v = fmaf(g1s[j], lin2_W[j], v);
        #pragma unroll
        for (int s = 16; s > 0; s >>= 1)
            v += __shfl_down_sync(0xffffffffu, v, s);
        if (tid == 0) out[gi] = v + lin2_b[0];
    }
}

// ---------------- launch: R15 fork/join + N-split edge1 -------------------------------
extern "C" void kernel_launch(void* const* d_in, const int* in_sizes, int n_in,
                              void* d_out, int out_size)
{
    const float* x      = (const float*)d_in[0];
    const float* ea     = (const float*)d_in[1];
    const void*  ei     = d_in[2];
    const void*  batch  = d_in[3];
    const float* nn1_W  = (const float*)d_in[4];
    const float* nn1_b  = (const float*)d_in[5];
    const float* root1  = (const float*)d_in[6];
    const float* bias1  = (const float*)d_in[7];
    const float* nn2_W  = (const float*)d_in[8];
    const float* nn2_b  = (const float*)d_in[9];
    const float* root2  = (const float*)d_in[10];
    const float* bias2  = (const float*)d_in[11];
    const float* lin1_W = (const float*)d_in[12];
    const float* lin1_b = (const float*)d_in[13];
    const float* lin2_W = (const float*)d_in[14];
    const float* lin2_b = (const float*)d_in[15];
    float* out = (float*)d_out;

    __half *xh, *h1h, *R1h, *R2h, *Y1r, *Y2r;
    cudaGetSymbolAddress((void**)&xh,  d_xh);
    cudaGetSymbolAddress((void**)&h1h, d_h1h);
    cudaGetSymbolAddress((void**)&R1h, d_R1h);
    cudaGetSymbolAddress((void**)&R2h, d_R2h);
    cudaGetSymbolAddress((void**)&Y1r, d_Y1r);
    cudaGetSymbolAddress((void**)&Y2r, d_Y2r);

    cudaStream_t s1;
    cudaStreamCreateWithFlags(&s1, cudaStreamNonBlocking);
    cudaEvent_t eFork1, eJoin1, eFork2, eJoin2;
    cudaEventCreateWithFlags(&eFork1, cudaEventDisableTiming);
    cudaEventCreateWithFlags(&eJoin1, cudaEventDisableTiming);
    cudaEventCreateWithFlags(&eFork2, cudaEventDisableTiming);
    cudaEventCreateWithFlags(&eJoin2, cudaEventDisableTiming);

    setup_kernel<<<NB_SETUP, 256>>>((const unsigned int*)ei, x,
                                    nn1_W, nn1_b, root1, nn2_W, nn2_b, root2);

    // fork: s1 runs root GEMM 1 then edge1 part B; main runs edge1 part A
    cudaEventRecord(eFork1, 0);
    cudaStreamWaitEvent(s1, eFork1, 0);
    gemm_mma<32, 32><<<dim3(2, 157), 128, 0, s1>>>(xh, N_NODES, R1h, Y1r, 128);
    edge_gemm1p<4, 3><<<(N_EDGES + 127) / 128, 256, 0, s1>>>(ea, ei);
    cudaEventRecord(eJoin1, s1);

    edge_gemm1p<0, 4><<<(N_EDGES + 127) / 128, 256>>>(ea, ei);
    cudaStreamWaitEvent(0, eJoin1, 0);
    node1ew<<<(N_NODES * 28 + 255) / 256, 256>>>(bias1);

    // fork: root GEMM 2 on s1, edge GEMM 2 on main
    cudaEventRecord(eFork2, 0);
    cudaStreamWaitEvent(s1, eFork2, 0);
    gemm_mma<112, 112><<<dim3(1, 157), 128, 0, s1>>>(h1h, N_NODES, R2h, Y2r, 64);
    cudaEventRecord(eJoin2, s1);

    edge_gemm2<<<(N_EDGES + 127) / 128, 256>>>(ea, ei);
    cudaStreamWaitEvent(0, eJoin2, 0);
    node2pool<<<(N_NODES * 5 + 255) / 256, 256>>>(bias2, batch);

    final_kernel<<<N_GRAPHS, 64>>>(lin1_W, lin1_b, lin2_W, lin2_b, out);
}